// round 2
// baseline (speedup 1.0000x reference)
#include <cuda_runtime.h>

// LIF SNN scan: T=1024 timesteps, B*N = 65536 independent columns.
// out layout: [ spikes (T*BN) | v_final (BN) | i_final (BN) ]
// R2: float2 vectorization (2 columns/thread) for 2x bytes-in-flight per
// outstanding load + streaming cache hints (zero-reuse 512MB stream).

#define T_STEPS 1024
#define BN      65536
#define NTHREADS (BN / 2)

__global__ __launch_bounds__(128, 8)
void snn_lif_kernel(const float2* __restrict__ x, float2* __restrict__ out) {
    const int idx = blockIdx.x * blockDim.x + threadIdx.x;  // float2-column id
    const float2* xp = x + idx;
    float2*       zp = out + idx;
    const int STRIDE = BN / 2;  // float2 elements per timestep

    float v0 = 0.0f, v1 = 0.0f;     // membrane potentials
    float c0 = 0.0f, c1 = 0.0f;     // synaptic currents

    // dt*tau_mem_inv = 0.1, (1 - dt*tau_syn_inv) = 0.8, v_th = 1, v_reset = 0
    #pragma unroll 16
    for (int t = 0; t < T_STEPS; ++t) {
        // independent of loop-carried state -> front-batched, high MLP
        const float2 xt = __ldcs(xp + (long)t * STRIDE);

        float2 z;

        const float vd0 = fmaf(0.1f, c0 - v0, v0);
        const bool  f0  = (vd0 > 1.0f);
        z.x = f0 ? 1.0f : 0.0f;
        v0  = f0 ? 0.0f : vd0;
        c0  = fmaf(c0, 0.8f, xt.x);

        const float vd1 = fmaf(0.1f, c1 - v1, v1);
        const bool  f1  = (vd1 > 1.0f);
        z.y = f1 ? 1.0f : 0.0f;
        v1  = f1 ? 0.0f : vd1;
        c1  = fmaf(c1, 0.8f, xt.y);

        __stcs(zp + (long)t * STRIDE, z);
    }

    // final state after the full scan: v then i, each BN floats (BN/2 float2)
    float2 vf; vf.x = v0; vf.y = v1;
    float2 cf; cf.x = c0; cf.y = c1;
    out[(long)T_STEPS * STRIDE + idx]          = vf;
    out[(long)T_STEPS * STRIDE + STRIDE + idx] = cf;
}

extern "C" void kernel_launch(void* const* d_in, const int* in_sizes, int n_in,
                              void* d_out, int out_size) {
    const float2* x   = (const float2*)d_in[0];
    float2*       out = (float2*)d_out;
    (void)in_sizes; (void)n_in; (void)out_size;

    snn_lif_kernel<<<NTHREADS / 128, 128>>>(x, out);
}

// round 3
// speedup vs baseline: 2.9830x; 2.9830x over previous
#include <cuda_runtime.h>

// LIF SNN scan: T=1024 timesteps, B*N = 65536 independent columns.
// out layout: [ spikes (T*BN) | v_final (BN) | i_final (BN) ]
// R3: explicit software-prefetch ring of depth 16 -> 16 LDGs structurally in
// flight per thread (4 MB chip-wide), instead of relying on ptxas batching.

#define T_STEPS 1024
#define BN      65536
#define PF      16

__global__ __launch_bounds__(128, 8)
void snn_lif_kernel(const float* __restrict__ x, float* __restrict__ out) {
    const int idx = blockIdx.x * blockDim.x + threadIdx.x;  // column id
    const float* xp = x + idx;
    float*       zp = out + idx;

    float v   = 0.0f;   // membrane potential
    float cur = 0.0f;   // synaptic current

    // prologue: fill the prefetch ring
    float xbuf[PF];
    #pragma unroll
    for (int j = 0; j < PF; ++j)
        xbuf[j] = __ldg(xp + (long)j * BN);

    // dt*tau_mem_inv = 0.1, (1 - dt*tau_syn_inv) = 0.8, v_th = 1, v_reset = 0
    for (int t0 = 0; t0 < T_STEPS - PF; t0 += PF) {
        #pragma unroll
        for (int j = 0; j < PF; ++j) {
            const float xt = xbuf[j];
            // immediately re-issue this slot for t0+PF+j (keeps PF loads in flight)
            xbuf[j] = __ldg(xp + (long)(t0 + PF + j) * BN);

            const float v_dec = fmaf(0.1f, cur - v, v);
            const bool  fired = (v_dec > 1.0f);
            const float z     = fired ? 1.0f : 0.0f;
            v   = fired ? 0.0f : v_dec;
            cur = fmaf(cur, 0.8f, xt);

            zp[(long)(t0 + j) * BN] = z;
        }
    }

    // epilogue: last PF steps, no prefetch
    #pragma unroll
    for (int j = 0; j < PF; ++j) {
        const float xt = xbuf[j];

        const float v_dec = fmaf(0.1f, cur - v, v);
        const bool  fired = (v_dec > 1.0f);
        const float z     = fired ? 1.0f : 0.0f;
        v   = fired ? 0.0f : v_dec;
        cur = fmaf(cur, 0.8f, xt);

        zp[(long)(T_STEPS - PF + j) * BN] = z;
    }

    // final state after the full scan
    out[(long)T_STEPS * BN + idx]      = v;
    out[(long)T_STEPS * BN + BN + idx] = cur;
}

extern "C" void kernel_launch(void* const* d_in, const int* in_sizes, int n_in,
                              void* d_out, int out_size) {
    const float* x   = (const float*)d_in[0];
    float*       out = (float*)d_out;
    (void)in_sizes; (void)n_in; (void)out_size;

    snn_lif_kernel<<<BN / 128, 128>>>(x, out);
}

// round 4
// speedup vs baseline: 3.3768x; 1.1320x over previous
#include <cuda_runtime.h>

// LIF SNN scan: T=1024 timesteps, B*N = 65536 independent columns.
// out layout: [ spikes (T*BN) | v_final (BN) | i_final (BN) ]
// R4: prefetch ring deepened 16 -> 32 (56 KB/SM in flight, 2.2x the
// latency-coverage knee). Grid-capped occupancy makes the extra regs free.

#define T_STEPS 1024
#define BN      65536
#define PF      32

__global__ __launch_bounds__(128, 4)
void snn_lif_kernel(const float* __restrict__ x, float* __restrict__ out) {
    const int idx = blockIdx.x * blockDim.x + threadIdx.x;  // column id
    const float* xp = x + idx;
    float*       zp = out + idx;

    float v   = 0.0f;   // membrane potential
    float cur = 0.0f;   // synaptic current

    // prologue: fill the prefetch ring (32 independent LDGs in flight)
    float xbuf[PF];
    #pragma unroll
    for (int j = 0; j < PF; ++j)
        xbuf[j] = __ldg(xp + (long)j * BN);

    // dt*tau_mem_inv = 0.1, (1 - dt*tau_syn_inv) = 0.8, v_th = 1, v_reset = 0
    for (int t0 = 0; t0 < T_STEPS - PF; t0 += PF) {
        #pragma unroll
        for (int j = 0; j < PF; ++j) {
            const float xt = xbuf[j];
            // immediately re-issue this slot for t0+PF+j (keeps PF loads in flight)
            xbuf[j] = __ldg(xp + (long)(t0 + PF + j) * BN);

            const float v_dec = fmaf(0.1f, cur - v, v);
            const bool  fired = (v_dec > 1.0f);
            const float z     = fired ? 1.0f : 0.0f;
            v   = fired ? 0.0f : v_dec;
            cur = fmaf(cur, 0.8f, xt);

            zp[(long)(t0 + j) * BN] = z;
        }
    }

    // epilogue: last PF steps, no prefetch
    #pragma unroll
    for (int j = 0; j < PF; ++j) {
        const float xt = xbuf[j];

        const float v_dec = fmaf(0.1f, cur - v, v);
        const bool  fired = (v_dec > 1.0f);
        const float z     = fired ? 1.0f : 0.0f;
        v   = fired ? 0.0f : v_dec;
        cur = fmaf(cur, 0.8f, xt);

        zp[(long)(T_STEPS - PF + j) * BN] = z;
    }

    // final state after the full scan
    out[(long)T_STEPS * BN + idx]      = v;
    out[(long)T_STEPS * BN + BN + idx] = cur;
}

extern "C" void kernel_launch(void* const* d_in, const int* in_sizes, int n_in,
                              void* d_out, int out_size) {
    const float* x   = (const float*)d_in[0];
    float*       out = (float*)d_out;
    (void)in_sizes; (void)n_in; (void)out_size;

    snn_lif_kernel<<<BN / 128, 128>>>(x, out);
}